// round 1
// baseline (speedup 1.0000x reference)
#include <cuda_runtime.h>
#include <math.h>

#define N_FFT   1024
#define HOP     256
#define NBINS   513
#define NMELS   128
#define BATCH   32
#define SIGLEN  160000
#define PAD     512
#define NFRAMES 626            // (160000+1024-1024)/256 + 1
#define NPAIRS  313            // 626/2
#define SUP     32             // max mel support (measured ~22)

// ---------------- device scratch (no allocations allowed) ----------------
__device__ float  g_mel[BATCH * NFRAMES * NMELS];   // ~10.3 MB
__device__ float  g_fbT[SUP * NMELS];               // compact transposed fb
__device__ int    g_start[NMELS];
__device__ int    g_maxlen;
__device__ float2 g_tw[N_FFT / 2];                  // exp(-2*pi*i*k/1024)

// ---------------- prep: compact fb + twiddles ----------------
__global__ void prep_kernel(const float* __restrict__ fb) {
    int m = threadIdx.x;   // 128 threads
    __shared__ int slen[NMELS];

    // twiddles (double precision generation)
    for (int k = m; k < N_FFT / 2; k += NMELS) {
        double ang = -2.0 * 3.14159265358979323846 * (double)k / (double)N_FFT;
        g_tw[k] = make_float2((float)cos(ang), (float)sin(ang));
    }

    // find nonzero support of column m
    int first = -1, last = -1;
    for (int f = 0; f < NBINS; f++) {
        float v = fb[f * NMELS + m];
        if (v != 0.0f) { if (first < 0) first = f; last = f; }
    }
    int st  = (first < 0) ? 0 : first;
    int len = (first < 0) ? 0 : (last - first + 1);
    if (len > SUP) len = SUP;   // safety clamp
    g_start[m] = st;
    for (int j = 0; j < SUP; j++)
        g_fbT[j * NMELS + m] = (j < len) ? fb[(st + j) * NMELS + m] : 0.0f;
    slen[m] = len;
    __syncthreads();
    if (m == 0) {
        int mx = 0;
        for (int i = 0; i < NMELS; i++) mx = max(mx, slen[i]);
        g_maxlen = mx;
    }
}

// ---------------- fft + mel: one block = 2 frames (packed real FFT) ------
__device__ __forceinline__ int reflect_idx(int src) {
    // src is index into unpadded signal coords, may be out of range
    if (src < 0) src = -src;
    if (src >= SIGLEN) src = 2 * SIGLEN - 2 - src;
    return src;
}

__global__ __launch_bounds__(256)
void fft_mel_kernel(const float* __restrict__ x) {
    __shared__ float  re[N_FFT];
    __shared__ float  im[N_FFT];
    __shared__ float2 tw[N_FFT / 2];
    __shared__ float  specA[NBINS + SUP];
    __shared__ float  specB[NBINS + SUP];
    __shared__ int    s_maxlen;

    const int tid = threadIdx.x;
    const int blk = blockIdx.x;
    const int b   = blk / NPAIRS;
    const int pr  = blk - b * NPAIRS;
    const int tA  = 2 * pr;
    const int tB  = tA + 1;

    const float* xb = x + (size_t)b * SIGLEN;

    // twiddle copy to shared
    #pragma unroll
    for (int k = tid; k < N_FFT / 2; k += 256) tw[k] = g_tw[k];
    if (tid == 0) s_maxlen = g_maxlen;

    // load both frames bit-reversed: re <- frame A, im <- frame B
    const int baseA = tA * HOP - PAD;   // xp offset minus pad = signal coord
    const int baseB = tB * HOP - PAD;
    #pragma unroll
    for (int k = 0; k < 4; k++) {
        int n   = tid + k * 256;
        int pos = __brev(n) >> 22;      // 10-bit reversal
        re[pos] = xb[reflect_idx(baseA + n)];
        im[pos] = xb[reflect_idx(baseB + n)];
    }
    __syncthreads();

    // radix-2 DIT, 10 stages
    #pragma unroll
    for (int s = 1; s <= 10; s++) {
        const int half = 1 << (s - 1);
        const int step = N_FFT >> s;     // twiddle stride
        #pragma unroll
        for (int q = 0; q < 2; q++) {
            int bfy = tid + q * 256;     // 0..511
            int j   = bfy & (half - 1);
            int i1  = ((bfy >> (s - 1)) << s) + j;
            int i2  = i1 + half;
            float2 w = tw[j * step];
            float r2 = re[i2], m2 = im[i2];
            float tr = w.x * r2 - w.y * m2;
            float ti = w.x * m2 + w.y * r2;
            float r1 = re[i1], m1 = im[i1];
            re[i2] = r1 - tr;  im[i2] = m1 - ti;
            re[i1] = r1 + tr;  im[i1] = m1 + ti;
        }
        __syncthreads();
    }

    // unpack packed real FFTs + magnitude
    #pragma unroll
    for (int k = tid; k < NBINS; k += 256) {
        int nk = (N_FFT - k) & (N_FFT - 1);
        float rk = re[k],  ik = im[k];
        float rn = re[nk], in = im[nk];
        float ar = 0.5f * (rk + rn);
        float ai = 0.5f * (ik - in);
        float br = 0.5f * (ik + in);
        float bi = 0.5f * (rn - rk);
        specA[k] = sqrtf(ar * ar + ai * ai);
        specB[k] = sqrtf(br * br + bi * bi);
    }
    // zero pad tails so the uniform mel loop never reads garbage
    for (int k = NBINS + tid; k < NBINS + SUP; k += 256) {
        specA[k] = 0.0f; specB[k] = 0.0f;
    }
    __syncthreads();

    // sparse mel projection: tid<128 -> frame A, tid>=128 -> frame B
    {
        int m = tid & (NMELS - 1);
        const float* spec = (tid < NMELS) ? specA : specB;
        int st = g_start[m];
        int ml = s_maxlen;
        float acc = 0.0f;
        for (int j = 0; j < ml; j++)
            acc += spec[st + j] * g_fbT[j * NMELS + m];
        int t = (tid < NMELS) ? tA : tB;
        g_mel[((size_t)b * NFRAMES + t) * NMELS + m] = acc;
    }
}

// ---------------- EMA + PCEN ----------------
__global__ __launch_bounds__(32)
void pcen_kernel(float* __restrict__ out) {
    const int b = blockIdx.x;
    const int m = blockIdx.y * 32 + threadIdx.x;
    const float* p = g_mel + ((size_t)b * NFRAMES) * NMELS + m;
    float*       o = out  + ((size_t)b * NFRAMES) * NMELS + m;

    const float SQ2 = 1.41421356237309515f;
    float v0 = p[0];
    float state = v0;
    o[0] = sqrtf(v0 * __powf(state + 1e-6f, -0.98f) + 2.0f) - SQ2;

    #pragma unroll 8
    for (int t = 1; t < NFRAMES; t++) {
        float v = p[(size_t)t * NMELS];
        state = state + 0.025f * (v - state);   // (1-s)*state + s*v
        o[(size_t)t * NMELS] =
            sqrtf(v * __powf(state + 1e-6f, -0.98f) + 2.0f) - SQ2;
    }
}

// ---------------- launch ----------------
extern "C" void kernel_launch(void* const* d_in, const int* in_sizes, int n_in,
                              void* d_out, int out_size) {
    const float* x  = (const float*)d_in[0];   // (32, 160000) f32
    const float* fb = (const float*)d_in[1];   // (513, 128)  f32
    float* out = (float*)d_out;                // (32, 626, 128) f32

    prep_kernel<<<1, NMELS>>>(fb);
    fft_mel_kernel<<<BATCH * NPAIRS, 256>>>(x);
    pcen_kernel<<<dim3(BATCH, NMELS / 32), 32>>>(out);
}

// round 2
// speedup vs baseline: 1.2604x; 1.2604x over previous
#include <cuda_runtime.h>
#include <math.h>

#define N_FFT   1024
#define HOP     256
#define NBINS   513
#define NMELS   128
#define BATCH   32
#define SIGLEN  160000
#define PAD     512
#define NFRAMES 626            // (160000+1024-1024)/256 + 1
#define NPAIRS  313            // 626/2
#define SUP     26             // max mel support (actual <=22) zero-padded

// ---------------- device scratch ----------------
__device__ float  g_mel[BATCH * NFRAMES * NMELS];   // ~10.3 MB
__device__ float  g_fbT[SUP * NMELS];               // compact transposed fb
__device__ int    g_start[NMELS];
__device__ float2 g_tw[N_FFT / 2];                  // exp(-2*pi*i*k/1024)

// ---------------- prep A: twiddles (parallel) ----------------
__global__ void prep_tw_kernel() {
    int k = blockIdx.x * 256 + threadIdx.x;   // 0..511
    float ang = -6.283185307179586f * (float)k / (float)N_FFT;
    float s, c;
    sincosf(ang, &s, &c);
    g_tw[k] = make_float2(c, s);
}

// ---------------- prep B: fb compaction, one warp per mel ---------------
__global__ void prep_fb_kernel(const float* __restrict__ fb) {
    const int m    = blockIdx.x;     // 0..127
    const int lane = threadIdx.x;    // 0..31

    int first = 0x7fffffff, last = -1;
    for (int f = lane; f < NBINS; f += 32) {
        float v = fb[f * NMELS + m];
        if (v != 0.0f) { first = min(first, f); last = max(last, f); }
    }
    first = __reduce_min_sync(0xffffffffu, first);
    last  = __reduce_max_sync(0xffffffffu, last);

    int st  = (last < 0) ? 0 : first;
    int len = (last < 0) ? 0 : (last - first + 1);
    if (len > SUP) len = SUP;

    if (lane == 0) g_start[m] = st;
    if (lane < SUP) {
        int j = lane;
        g_fbT[j * NMELS + m] = (j < len) ? fb[(st + j) * NMELS + m] : 0.0f;
    }
}

// ---------------- fft + mel: one block = 2 frames, radix-4 --------------
__device__ __forceinline__ int reflect_idx(int src) {
    if (src < 0) src = -src;
    if (src >= SIGLEN) src = 2 * SIGLEN - 2 - src;
    return src;
}
__device__ __forceinline__ float2 cmul(float2 a, float2 b) {
    return make_float2(a.x * b.x - a.y * b.y, a.x * b.y + a.y * b.x);
}

__global__ __launch_bounds__(256)
void fft_mel_kernel(const float* __restrict__ x) {
    __shared__ float  re[N_FFT];
    __shared__ float  im[N_FFT];
    __shared__ float2 tw[N_FFT / 2];
    __shared__ float  specA[NBINS + SUP + 1];
    __shared__ float  specB[NBINS + SUP + 1];

    const int tid = threadIdx.x;
    const int blk = blockIdx.x;
    const int b   = blk / NPAIRS;
    const int pr  = blk - b * NPAIRS;
    const int tA  = 2 * pr;
    const int tB  = tA + 1;

    const float* xb = x + (size_t)b * SIGLEN;

    // twiddles to shared
    tw[tid]       = g_tw[tid];
    tw[tid + 256] = g_tw[tid + 256];

    // load both frames base-4-digit-reversed: re <- A, im <- B
    const int baseA = tA * HOP - PAD;
    const int baseB = tB * HOP - PAD;
    #pragma unroll
    for (int k = 0; k < 4; k++) {
        int n = tid + k * 256;
        int r = __brev(n) >> 22;                          // 10-bit bitrev
        int pos = ((r & 0x155) << 1) | ((r & 0x2AA) >> 1); // swap bit pairs
        re[pos] = xb[reflect_idx(baseA + n)];
        im[pos] = xb[reflect_idx(baseB + n)];
    }
    __syncthreads();

    // radix-4 DIT, 5 stages, 256 butterflies each (one per thread)
    #pragma unroll
    for (int s = 0; s < 5; s++) {
        const int m  = 1 << (2 * s);
        const int ts = 256 >> (2 * s);          // twiddle stride = 256/m
        const int j  = tid & (m - 1);
        const int g  = tid >> (2 * s);
        const int i0 = (g << (2 * s + 2)) + j;

        float2 w1 = tw[j * ts];
        float2 w2 = tw[2 * j * ts];
        float2 w3 = cmul(w1, w2);

        float2 a = make_float2(re[i0],         im[i0]);
        float2 bb= make_float2(re[i0 + m],     im[i0 + m]);
        float2 c = make_float2(re[i0 + 2 * m], im[i0 + 2 * m]);
        float2 d = make_float2(re[i0 + 3 * m], im[i0 + 3 * m]);
        bb = cmul(bb, w1);
        c  = cmul(c,  w2);
        d  = cmul(d,  w3);

        float t0x = a.x + c.x,  t0y = a.y + c.y;
        float t1x = a.x - c.x,  t1y = a.y - c.y;
        float t2x = bb.x + d.x, t2y = bb.y + d.y;
        float t3x = bb.x - d.x, t3y = bb.y - d.y;

        __syncthreads();   // protect reads before overwriting (in-place)
        re[i0]         = t0x + t2x;  im[i0]         = t0y + t2y;
        re[i0 + m]     = t1x + t3y;  im[i0 + m]     = t1y - t3x;  // t1 - i*t3
        re[i0 + 2 * m] = t0x - t2x;  im[i0 + 2 * m] = t0y - t2y;
        re[i0 + 3 * m] = t1x - t3y;  im[i0 + 3 * m] = t1y + t3x;  // t1 + i*t3
        __syncthreads();
    }

    // unpack packed real FFTs + magnitude
    #pragma unroll
    for (int k = tid; k < NBINS; k += 256) {
        int nk = (N_FFT - k) & (N_FFT - 1);
        float rk = re[k],  ik = im[k];
        float rn = re[nk], in = im[nk];
        float ar = 0.5f * (rk + rn);
        float ai = 0.5f * (ik - in);
        float br = 0.5f * (ik + in);
        float bi = 0.5f * (rn - rk);
        specA[k] = sqrtf(ar * ar + ai * ai);
        specB[k] = sqrtf(br * br + bi * bi);
    }
    for (int k = NBINS + tid; k < NBINS + SUP; k += 256) {
        specA[k] = 0.0f; specB[k] = 0.0f;
    }
    __syncthreads();

    // sparse mel: tid<128 -> frame A, tid>=128 -> frame B
    {
        int m = tid & (NMELS - 1);
        const float* spec = (tid < NMELS) ? specA : specB;
        int st = g_start[m];
        float acc = 0.0f;
        #pragma unroll
        for (int j = 0; j < SUP; j++)
            acc += spec[st + j] * g_fbT[j * NMELS + m];
        int t = (tid < NMELS) ? tA : tB;
        g_mel[((size_t)b * NFRAMES + t) * NMELS + m] = acc;
    }
}

// ---------------- EMA + PCEN ----------------
__global__ __launch_bounds__(128)
void pcen_kernel(float* __restrict__ out) {
    const int b = blockIdx.x;
    const int m = threadIdx.x;
    const float* p = g_mel + ((size_t)b * NFRAMES) * NMELS + m;
    float*       o = out  + ((size_t)b * NFRAMES) * NMELS + m;

    const float SQ2 = 1.41421356237309515f;
    float v0 = p[0];
    float state = v0;
    o[0] = sqrtf(v0 * __powf(state + 1e-6f, -0.98f) + 2.0f) - SQ2;

    #pragma unroll 8
    for (int t = 1; t < NFRAMES; t++) {
        float v = p[(size_t)t * NMELS];
        state = fmaf(0.025f, v - state, state);   // (1-s)*state + s*v
        o[(size_t)t * NMELS] =
            sqrtf(v * __powf(state + 1e-6f, -0.98f) + 2.0f) - SQ2;
    }
}

// ---------------- launch ----------------
extern "C" void kernel_launch(void* const* d_in, const int* in_sizes, int n_in,
                              void* d_out, int out_size) {
    const float* x  = (const float*)d_in[0];   // (32, 160000) f32
    const float* fb = (const float*)d_in[1];   // (513, 128)  f32
    float* out = (float*)d_out;                // (32, 626, 128) f32

    prep_tw_kernel<<<2, 256>>>();
    prep_fb_kernel<<<NMELS, 32>>>(fb);
    fft_mel_kernel<<<BATCH * NPAIRS, 256>>>(x);
    pcen_kernel<<<BATCH, NMELS>>>(out);
}

// round 3
// speedup vs baseline: 2.4249x; 1.9239x over previous
#include <cuda_runtime.h>
#include <math.h>

#define N_FFT   1024
#define HOP     256
#define NBINS   513
#define NMELS   128
#define BATCH   32
#define SIGLEN  160000
#define PAD     512
#define NFRAMES 626            // (160000+1024-1024)/256 + 1
#define NPAIRS  313            // 626/2
#define SUP     26             // max mel support (actual <=22) zero-padded

#define KCH     32             // EMA chunks per chain
#define LCH     20             // frames per chunk (31*20 + 6 = 626)
#define EMA_A   0.975f
#define EMA_S   0.025f

// ---------------- device scratch ----------------
__device__ float  g_mel[BATCH * NFRAMES * NMELS];   // ~10.3 MB
__device__ float  g_T  [BATCH * KCH * NMELS];       // per-chunk partial states
__device__ float  g_Sin[BATCH * KCH * NMELS];       // per-chunk incoming states
__device__ float  g_fbT[SUP * NMELS];               // compact transposed fb
__device__ int    g_start[NMELS];
__device__ float2 g_tw[N_FFT / 2];                  // exp(-2*pi*i*k/1024)

// ---------------- prep A: twiddles ----------------
__global__ void prep_tw_kernel() {
    int k = blockIdx.x * 256 + threadIdx.x;   // 0..511
    float ang = -6.283185307179586f * (float)k / (float)N_FFT;
    float s, c;
    sincosf(ang, &s, &c);
    g_tw[k] = make_float2(c, s);
}

// ---------------- prep B: fb compaction, one warp per mel ---------------
__global__ void prep_fb_kernel(const float* __restrict__ fb) {
    const int m    = blockIdx.x;     // 0..127
    const int lane = threadIdx.x;    // 0..31

    int first = 0x7fffffff, last = -1;
    for (int f = lane; f < NBINS; f += 32) {
        float v = fb[f * NMELS + m];
        if (v != 0.0f) { first = min(first, f); last = max(last, f); }
    }
    first = __reduce_min_sync(0xffffffffu, first);
    last  = __reduce_max_sync(0xffffffffu, last);

    int st  = (last < 0) ? 0 : first;
    int len = (last < 0) ? 0 : (last - first + 1);
    if (len > SUP) len = SUP;

    if (lane == 0) g_start[m] = st;
    if (lane < SUP) {
        int j = lane;
        g_fbT[j * NMELS + m] = (j < len) ? fb[(st + j) * NMELS + m] : 0.0f;
    }
}

// ---------------- fft + mel: one block = 2 frames, radix-4 --------------
__device__ __forceinline__ int reflect_idx(int src) {
    if (src < 0) src = -src;
    if (src >= SIGLEN) src = 2 * SIGLEN - 2 - src;
    return src;
}
__device__ __forceinline__ float2 cmul(float2 a, float2 b) {
    return make_float2(a.x * b.x - a.y * b.y, a.x * b.y + a.y * b.x);
}

__global__ __launch_bounds__(256)
void fft_mel_kernel(const float* __restrict__ x) {
    __shared__ float  re[N_FFT];
    __shared__ float  im[N_FFT];
    __shared__ float2 tw[N_FFT / 2];
    __shared__ float  specA[NBINS + SUP + 1];
    __shared__ float  specB[NBINS + SUP + 1];

    const int tid = threadIdx.x;
    const int blk = blockIdx.x;
    const int b   = blk / NPAIRS;
    const int pr  = blk - b * NPAIRS;
    const int tA  = 2 * pr;
    const int tB  = tA + 1;

    const float* xb = x + (size_t)b * SIGLEN;

    tw[tid]       = g_tw[tid];
    tw[tid + 256] = g_tw[tid + 256];

    const int baseA = tA * HOP - PAD;
    const int baseB = tB * HOP - PAD;
    #pragma unroll
    for (int k = 0; k < 4; k++) {
        int n = tid + k * 256;
        int r = __brev(n) >> 22;                           // 10-bit bitrev
        int pos = ((r & 0x155) << 1) | ((r & 0x2AA) >> 1); // base-4 digit rev
        re[pos] = xb[reflect_idx(baseA + n)];
        im[pos] = xb[reflect_idx(baseB + n)];
    }
    __syncthreads();

    #pragma unroll
    for (int s = 0; s < 5; s++) {
        const int m  = 1 << (2 * s);
        const int ts = 256 >> (2 * s);
        const int j  = tid & (m - 1);
        const int g  = tid >> (2 * s);
        const int i0 = (g << (2 * s + 2)) + j;

        float2 w1 = tw[j * ts];
        float2 w2 = tw[2 * j * ts];
        float2 w3 = cmul(w1, w2);

        float2 a = make_float2(re[i0],         im[i0]);
        float2 bb= make_float2(re[i0 + m],     im[i0 + m]);
        float2 c = make_float2(re[i0 + 2 * m], im[i0 + 2 * m]);
        float2 d = make_float2(re[i0 + 3 * m], im[i0 + 3 * m]);
        bb = cmul(bb, w1);
        c  = cmul(c,  w2);
        d  = cmul(d,  w3);

        float t0x = a.x + c.x,  t0y = a.y + c.y;
        float t1x = a.x - c.x,  t1y = a.y - c.y;
        float t2x = bb.x + d.x, t2y = bb.y + d.y;
        float t3x = bb.x - d.x, t3y = bb.y - d.y;

        __syncthreads();
        re[i0]         = t0x + t2x;  im[i0]         = t0y + t2y;
        re[i0 + m]     = t1x + t3y;  im[i0 + m]     = t1y - t3x;
        re[i0 + 2 * m] = t0x - t2x;  im[i0 + 2 * m] = t0y - t2y;
        re[i0 + 3 * m] = t1x - t3y;  im[i0 + 3 * m] = t1y + t3x;
        __syncthreads();
    }

    #pragma unroll
    for (int k = tid; k < NBINS; k += 256) {
        int nk = (N_FFT - k) & (N_FFT - 1);
        float rk = re[k],  ik = im[k];
        float rn = re[nk], in = im[nk];
        float ar = 0.5f * (rk + rn);
        float ai = 0.5f * (ik - in);
        float br = 0.5f * (ik + in);
        float bi = 0.5f * (rn - rk);
        specA[k] = sqrtf(ar * ar + ai * ai);
        specB[k] = sqrtf(br * br + bi * bi);
    }
    for (int k = NBINS + tid; k < NBINS + SUP; k += 256) {
        specA[k] = 0.0f; specB[k] = 0.0f;
    }
    __syncthreads();

    {
        int m = tid & (NMELS - 1);
        const float* spec = (tid < NMELS) ? specA : specB;
        int st = g_start[m];
        float acc = 0.0f;
        #pragma unroll
        for (int j = 0; j < SUP; j++)
            acc += spec[st + j] * g_fbT[j * NMELS + m];
        int t = (tid < NMELS) ? tA : tB;
        g_mel[((size_t)b * NFRAMES + t) * NMELS + m] = acc;
    }
}

// ---------------- PCEN stage 1: per-chunk partial EMA (zero-input) ------
__global__ __launch_bounds__(128)
void pcen_part1_kernel() {
    const int m = threadIdx.x;        // 0..127
    const int b = blockIdx.x;         // 0..31
    const int c = blockIdx.y;         // 0..KCH-1

    const int t0 = c * LCH;
    const int t1 = min(t0 + LCH, NFRAMES);
    const float* p = g_mel + ((size_t)b * NFRAMES + t0) * NMELS + m;

    float state;
    int tstart;
    if (c == 0) {                     // chunk 0 seeds with v0 (m_0 = v_0)
        state  = p[0];
        tstart = 1;
    } else {                          // zero incoming state
        state  = 0.0f;
        tstart = 0;
    }
    #pragma unroll
    for (int t = tstart; t < LCH; t++) {
        if (t0 + t >= t1) break;
        float v = p[(size_t)t * NMELS];
        state = fmaf(EMA_A, state, EMA_S * v);
    }
    g_T[((size_t)b * KCH + c) * NMELS + m] = state;
}

// ---------------- PCEN stage 2: serial chunk prefix (tiny) --------------
__global__ __launch_bounds__(128)
void pcen_combine_kernel() {
    const int m = threadIdx.x;
    const int b = blockIdx.x;

    float Tv[KCH];
    #pragma unroll
    for (int c = 0; c < KCH; c++)
        Tv[c] = g_T[((size_t)b * KCH + c) * NMELS + m];

    // a^LCH as a constant-folded product (matches float rounding profile)
    float A = 1.0f;
    #pragma unroll
    for (int i = 0; i < LCH; i++) A *= EMA_A;

    float S = 0.0f;
    #pragma unroll
    for (int c = 0; c < KCH; c++) {
        g_Sin[((size_t)b * KCH + c) * NMELS + m] = S;
        S = fmaf(A, S, Tv[c]);
    }
}

// ---------------- PCEN stage 3: outputs ----------------------------------
__device__ __forceinline__ float pcen_f(float v, float M) {
    float p = exp2f(-0.98f * __log2f(M + 1e-6f));     // (M+eps)^-0.98
    float y = fmaf(v, p, 2.0f);                        // v*p + 2
    return y * rsqrtf(y) - 1.41421356237309515f;       // sqrt(y) - sqrt(2)
}

__global__ __launch_bounds__(128)
void pcen_part2_kernel(float* __restrict__ out) {
    const int m = threadIdx.x;
    const int b = blockIdx.x;
    const int c = blockIdx.y;

    const int t0 = c * LCH;
    const int t1 = min(t0 + LCH, NFRAMES);
    const float* p = g_mel + ((size_t)b * NFRAMES + t0) * NMELS + m;
    float*       o = out  + ((size_t)b * NFRAMES + t0) * NMELS + m;

    float state;
    int tstart;
    if (c == 0) {
        float v0 = p[0];
        state = v0;
        o[0] = pcen_f(v0, state);
        tstart = 1;
    } else {
        state = g_Sin[((size_t)b * KCH + c) * NMELS + m];
        tstart = 0;
    }
    #pragma unroll
    for (int t = tstart; t < LCH; t++) {
        if (t0 + t >= t1) break;
        float v = p[(size_t)t * NMELS];
        state = fmaf(EMA_A, state, EMA_S * v);
        o[(size_t)t * NMELS] = pcen_f(v, state);
    }
}

// ---------------- launch ----------------
extern "C" void kernel_launch(void* const* d_in, const int* in_sizes, int n_in,
                              void* d_out, int out_size) {
    const float* x  = (const float*)d_in[0];   // (32, 160000) f32
    const float* fb = (const float*)d_in[1];   // (513, 128)  f32
    float* out = (float*)d_out;                // (32, 626, 128) f32

    prep_tw_kernel<<<2, 256>>>();
    prep_fb_kernel<<<NMELS, 32>>>(fb);
    fft_mel_kernel<<<BATCH * NPAIRS, 256>>>(x);
    pcen_part1_kernel<<<dim3(BATCH, KCH), 128>>>();
    pcen_combine_kernel<<<BATCH, 128>>>();
    pcen_part2_kernel<<<dim3(BATCH, KCH), 128>>>(out);
}

// round 5
// speedup vs baseline: 2.6791x; 1.1049x over previous
#include <cuda_runtime.h>
#include <math.h>

#define N_FFT   1024
#define HOP     256
#define NBINS   513
#define NMELS   128
#define BATCH   32
#define SIGLEN  160000
#define PAD     512
#define NFRAMES 626
#define SUP     26
#define FPB     8              // frames per block
#define NFBLK   79             // ceil(626/8)
#define CFFT    4              // complex FFTs per block (2 frames each)
#define MPITCH  33
#define MSZ     (32 * MPITCH)  // 1056 floats per matrix

#define KCH     32             // EMA chunks per chain
#define LCH     20             // frames per chunk
#define EMA_A   0.975f
#define EMA_S   0.025f

// ---------------- device scratch ----------------
__device__ float  g_mel[BATCH * NFRAMES * NMELS];
__device__ float  g_T  [BATCH * KCH * NMELS];      // zero-init; chunk 31 stays 0
__device__ float  g_Sin[BATCH * KCH * NMELS];
__device__ float  g_fbT[SUP * NMELS];
__device__ int    g_start[NMELS];
__device__ float2 g_tw[N_FFT];                     // exp(-2*pi*i*k/1024), k<1024

// ---------------- prep A: twiddles ----------------
__global__ void prep_tw_kernel() {
    int k = blockIdx.x * 256 + threadIdx.x;        // grid 4 -> 0..1023
    float ang = -6.283185307179586f * (float)k / (float)N_FFT;
    float s, c;
    sincosf(ang, &s, &c);
    g_tw[k] = make_float2(c, s);
}

// ---------------- prep B: fb compaction, one warp per mel ---------------
__global__ void prep_fb_kernel(const float* __restrict__ fb) {
    const int m    = blockIdx.x;
    const int lane = threadIdx.x;

    int first = 0x7fffffff, last = -1;
    for (int f = lane; f < NBINS; f += 32) {
        float v = fb[f * NMELS + m];
        if (v != 0.0f) { first = min(first, f); last = max(last, f); }
    }
    first = __reduce_min_sync(0xffffffffu, first);
    last  = __reduce_max_sync(0xffffffffu, last);

    int st  = (last < 0) ? 0 : first;
    int len = (last < 0) ? 0 : (last - first + 1);
    if (len > SUP) len = SUP;

    if (lane == 0) g_start[m] = st;
    if (lane < SUP) {
        int j = lane;
        g_fbT[j * NMELS + m] = (j < len) ? fb[(st + j) * NMELS + m] : 0.0f;
    }
}

// ---------------- in-register FFT32 helpers ----------------
__host__ __device__ constexpr int brev5(int i) {
    return ((i & 1) << 4) | ((i & 2) << 2) | (i & 4) | ((i & 8) >> 2) | ((i & 16) >> 4);
}
__device__ __forceinline__ constexpr float w32r(int j) {
    return (j == 0) ?  1.0f :
           (j == 1) ?  0.980785280403230f :
           (j == 2) ?  0.923879532511287f :
           (j == 3) ?  0.831469612302545f :
           (j == 4) ?  0.707106781186548f :
           (j == 5) ?  0.555570233019602f :
           (j == 6) ?  0.382683432365090f :
           (j == 7) ?  0.195090322016128f :
           (j == 8) ?  0.0f :
           (j == 9) ? -0.195090322016128f :
           (j ==10) ? -0.382683432365090f :
           (j ==11) ? -0.555570233019602f :
           (j ==12) ? -0.707106781186548f :
           (j ==13) ? -0.831469612302545f :
           (j ==14) ? -0.923879532511287f :
                      -0.980785280403230f;
}
__device__ __forceinline__ constexpr float w32i(int j) {
    return (j == 0) ?  0.0f :
           (j == 1) ? -0.195090322016128f :
           (j == 2) ? -0.382683432365090f :
           (j == 3) ? -0.555570233019602f :
           (j == 4) ? -0.707106781186548f :
           (j == 5) ? -0.831469612302545f :
           (j == 6) ? -0.923879532511287f :
           (j == 7) ? -0.980785280403230f :
           (j == 8) ? -1.0f :
           (j == 9) ? -0.980785280403230f :
           (j ==10) ? -0.923879532511287f :
           (j ==11) ? -0.831469612302545f :
           (j ==12) ? -0.707106781186548f :
           (j ==13) ? -0.555570233019602f :
           (j ==14) ? -0.382683432365090f :
                      -0.195090322016128f;
}

// input in bit-reversed order, output natural order
__device__ __forceinline__ void fft32(float xr[32], float xi[32]) {
    #pragma unroll
    for (int s = 0; s < 5; s++) {
        const int half = 1 << s;
        #pragma unroll
        for (int g = 0; g < (16 >> s); g++) {
            #pragma unroll
            for (int j = 0; j < half; j++) {
                const int i1 = g * 2 * half + j;
                const int i2 = i1 + half;
                const float wr = w32r(j << (4 - s));
                const float wi = w32i(j << (4 - s));
                float tr = xr[i2] * wr - xi[i2] * wi;
                float ti = xr[i2] * wi + xi[i2] * wr;
                xr[i2] = xr[i1] - tr;  xi[i2] = xi[i1] - ti;
                xr[i1] += tr;          xi[i1] += ti;
            }
        }
    }
}

__device__ __forceinline__ int reflect_idx(int src) {
    if (src < 0) src = -src;
    if (src >= SIGLEN) src = 2 * SIGLEN - 2 - src;
    return src;
}

// ---------------- fft + mel: 32x32 two-pass register FFT ----------------
__global__ __launch_bounds__(128)
void fft_mel_kernel(const float* __restrict__ x) {
    __shared__ float Sre[CFFT * MSZ];   // 16.9 KB
    __shared__ float Sim[CFFT * MSZ];   // 16.9 KB

    const int tid   = threadIdx.x;
    const int q     = tid >> 5;         // cFFT index 0..3
    const int ln    = tid & 31;         // lane
    const int b     = blockIdx.y;
    const int fbase = blockIdx.x * FPB;

    const float* xb = x + (size_t)b * SIGLEN;
    float* mre = Sre + q * MSZ;
    float* mim = Sim + q * MSZ;

    // ---- load frames (2q, 2q+1) packed as re/im, layout M[n2][n1] ----
    const int baseA = (fbase + 2 * q) * HOP - PAD;
    const int baseB = baseA + HOP;
    if (baseA >= 0 && baseB + N_FFT <= SIGLEN) {
        #pragma unroll
        for (int j = 0; j < 32; j++) {
            int n = ln + 32 * j;
            mre[MPITCH * j + ln] = xb[baseA + n];
            mim[MPITCH * j + ln] = xb[baseB + n];
        }
    } else {
        #pragma unroll 4
        for (int j = 0; j < 32; j++) {
            int n = ln + 32 * j;
            mre[MPITCH * j + ln] = xb[reflect_idx(baseA + n)];
            mim[MPITCH * j + ln] = xb[reflect_idx(baseB + n)];
        }
    }
    __syncwarp();

    float xr[32], xi[32];

    // ---- pass 1: FFT32 over n2 (this thread = column n1 = ln) ----
    #pragma unroll
    for (int i = 0; i < 32; i++) {
        const int r = brev5(i);
        xr[i] = mre[MPITCH * r + ln];
        xi[i] = mim[MPITCH * r + ln];
    }
    fft32(xr, xi);

    // twiddle W^{n1*k2} and store transposed: M[k2][n1]
    #pragma unroll
    for (int k2 = 0; k2 < 32; k2++) {
        float2 w = g_tw[(ln * k2) & (N_FFT - 1)];
        float tr = xr[k2] * w.x - xi[k2] * w.y;
        float ti = xr[k2] * w.y + xi[k2] * w.x;
        mre[MPITCH * k2 + ln] = tr;
        mim[MPITCH * k2 + ln] = ti;
    }
    __syncwarp();

    // ---- pass 2: FFT32 over n1 (this thread = row k2 = ln) ----
    #pragma unroll
    for (int i = 0; i < 32; i++) {
        const int r = brev5(i);
        xr[i] = mre[MPITCH * ln + r];
        xi[i] = mim[MPITCH * ln + r];
    }
    __syncwarp();          // all lanes done reading M before spec overlay
    fft32(xr, xi);         // now xr/xi[k1] = X[ln + 32*k1]

    // ---- conjugate unpack via shuffles, spec overlays M region ----
    float* sA = mre;       // spec frame A: [0..512] + pad [513..538]
    float* sB = mim;
    const int lnp = (32 - ln) & 31;
    #pragma unroll
    for (int k1 = 0; k1 < 16; k1++) {
        float pr = __shfl_sync(0xffffffffu, xr[31 - k1], lnp);
        float pi = __shfl_sync(0xffffffffu, xi[31 - k1], lnp);
        if (ln == 0) { pr = xr[(32 - k1) & 31]; pi = xi[(32 - k1) & 31]; }
        float ar = 0.5f * (xr[k1] + pr), ai = 0.5f * (xi[k1] - pi);
        float br = 0.5f * (xi[k1] + pi), bi = 0.5f * (pr - xr[k1]);
        sA[ln + 32 * k1] = sqrtf(ar * ar + ai * ai);
        sB[ln + 32 * k1] = sqrtf(br * br + bi * bi);
    }
    if (ln == 0) { sA[512] = fabsf(xr[16]); sB[512] = fabsf(xi[16]); }
    if (ln < SUP) { sA[513 + ln] = 0.0f; sB[513 + ln] = 0.0f; }
    __syncthreads();       // the only block-wide barrier

    // ---- sparse mel: thread = mel channel, all 8 frames ----
    {
        const int m  = tid;
        const int st = g_start[m];
        float acc[FPB];
        #pragma unroll
        for (int f = 0; f < FPB; f++) acc[f] = 0.0f;
        #pragma unroll
        for (int j = 0; j < SUP; j++) {
            float fv = g_fbT[j * NMELS + m];
            #pragma unroll
            for (int f = 0; f < FPB; f++) {
                const float* sp = ((f & 1) ? Sim : Sre) + (f >> 1) * MSZ;
                acc[f] += sp[st + j] * fv;
            }
        }
        #pragma unroll
        for (int f = 0; f < FPB; f++) {
            int frame = fbase + f;
            if (frame < NFRAMES)
                g_mel[((size_t)b * NFRAMES + frame) * NMELS + m] = acc[f];
        }
    }
}

// ---------------- PCEN stage 1: per-chunk partial EMA (c = 0..30) -------
__global__ __launch_bounds__(128)
void pcen_part1_kernel() {
    const int m = threadIdx.x;
    const int b = blockIdx.x;
    const int c = blockIdx.y;          // 0..KCH-2 (all full chunks)

    const float* p = g_mel + ((size_t)b * NFRAMES + c * LCH) * NMELS + m;

    float state;
    if (c == 0) {
        state = p[0];
        #pragma unroll
        for (int t = 1; t < LCH; t++) {
            float v = p[(size_t)t * NMELS];
            state = fmaf(EMA_A, state, EMA_S * v);
        }
    } else {
        state = 0.0f;
        #pragma unroll
        for (int t = 0; t < LCH; t++) {
            float v = p[(size_t)t * NMELS];
            state = fmaf(EMA_A, state, EMA_S * v);
        }
    }
    g_T[((size_t)b * KCH + c) * NMELS + m] = state;
}

// ---------------- PCEN stage 2: serial chunk prefix ---------------------
__global__ __launch_bounds__(128)
void pcen_combine_kernel() {
    const int m = threadIdx.x;
    const int b = blockIdx.x;

    float Tv[KCH];
    #pragma unroll
    for (int c = 0; c < KCH; c++)
        Tv[c] = g_T[((size_t)b * KCH + c) * NMELS + m];

    float A = 1.0f;
    #pragma unroll
    for (int i = 0; i < LCH; i++) A *= EMA_A;

    float S = 0.0f;
    #pragma unroll
    for (int c = 0; c < KCH; c++) {
        g_Sin[((size_t)b * KCH + c) * NMELS + m] = S;
        S = fmaf(A, S, Tv[c]);
    }
}

// ---------------- PCEN stage 3: outputs ----------------------------------
__device__ __forceinline__ float pcen_f(float v, float M) {
    float pw = exp2f(-0.98f * __log2f(M + 1e-6f));     // (M+eps)^-0.98
    float y  = fmaf(v, pw, 2.0f);
    return y * rsqrtf(y) - 1.41421356237309515f;       // sqrt(y) - sqrt(2)
}

__global__ __launch_bounds__(128)
void pcen_part2_kernel(float* __restrict__ out) {
    const int m = threadIdx.x;
    const int b = blockIdx.x;
    const int c = blockIdx.y;

    const int t0 = c * LCH;
    const float* p = g_mel + ((size_t)b * NFRAMES + t0) * NMELS + m;
    float*       o = out  + ((size_t)b * NFRAMES + t0) * NMELS + m;

    if (c == 0) {
        float v0 = p[0];
        float state = v0;
        o[0] = pcen_f(v0, state);
        #pragma unroll
        for (int t = 1; t < LCH; t++) {
            float v = p[(size_t)t * NMELS];
            state = fmaf(EMA_A, state, EMA_S * v);
            o[(size_t)t * NMELS] = pcen_f(v, state);
        }
    } else if (c < KCH - 1) {
        float state = g_Sin[((size_t)b * KCH + c) * NMELS + m];
        #pragma unroll
        for (int t = 0; t < LCH; t++) {
            float v = p[(size_t)t * NMELS];
            state = fmaf(EMA_A, state, EMA_S * v);
            o[(size_t)t * NMELS] = pcen_f(v, state);
        }
    } else {
        float state = g_Sin[((size_t)b * KCH + c) * NMELS + m];
        #pragma unroll
        for (int t = 0; t < NFRAMES - (KCH - 1) * LCH; t++) {   // 6 frames
            float v = p[(size_t)t * NMELS];
            state = fmaf(EMA_A, state, EMA_S * v);
            o[(size_t)t * NMELS] = pcen_f(v, state);
        }
    }
}

// ---------------- launch ----------------
extern "C" void kernel_launch(void* const* d_in, const int* in_sizes, int n_in,
                              void* d_out, int out_size) {
    const float* x  = (const float*)d_in[0];   // (32, 160000) f32
    const float* fb = (const float*)d_in[1];   // (513, 128)  f32
    float* out = (float*)d_out;                // (32, 626, 128) f32

    prep_tw_kernel<<<4, 256>>>();
    prep_fb_kernel<<<NMELS, 32>>>(fb);
    fft_mel_kernel<<<dim3(NFBLK, BATCH), 128>>>(x);
    pcen_part1_kernel<<<dim3(BATCH, KCH - 1), 128>>>();
    pcen_combine_kernel<<<BATCH, 128>>>();
    pcen_part2_kernel<<<dim3(BATCH, KCH), 128>>>(out);
}